// round 8
// baseline (speedup 1.0000x reference)
#include <cuda_runtime.h>

#define N_PLANES 73
#define BOARD 8
#define FLAT (N_PLANES * BOARD * BOARD)   // 4672
#define N_MOVES 1858
#define BATCH 4096
#define ROWS 2                            // batch rows per gather block
#define OUT4 ((ROWS * N_MOVES) / 4)       // 929 float4 stores per block
#define PAIR4 (ROWS * FLAT / 4)           // 2336 float4 smem fill per block

#define N4 ((FLAT * N_MOVES) / 4)         // 2,170,144 float4s in W
#define E_CHUNK 2048                      // float4s per extract block (8/thread)
#define E_BLOCKS ((N4 + E_CHUNK - 1) / E_CHUNK)   // 1060

// Scratch for extracted one-hot row indices (device mallocs banned).
__device__ __align__(16) int g_idx[N_MOVES];

// ---------------------------------------------------------------------------
// Kernel 1: recover idx[j] = r with W[r][j] == 1.0.
// Each block owns 2048 contiguous float4s; each thread issues 8 back-to-back
// coalesced loads (MLP=8). Plain loads -> W stays L2-resident across replays.
// ---------------------------------------------------------------------------
__global__ __launch_bounds__(256)
void extract_idx_kernel(const float4* __restrict__ W4,
                        int* __restrict__ idx) {
    const int base = blockIdx.x * E_CHUNK + threadIdx.x;

    float4 v[8];
    #pragma unroll
    for (int k = 0; k < 8; k++) {
        int i = base + k * 256;
        v[k] = (i < N4) ? W4[i] : make_float4(0.f, 0.f, 0.f, 0.f);
    }

    #pragma unroll
    for (int k = 0; k < 8; k++) {
        if (v[k].x != 0.f || v[k].y != 0.f || v[k].z != 0.f || v[k].w != 0.f) {
            long e = (long)(base + k * 256) * 4;
            if (v[k].x != 0.f) { long t = e;     idx[t % N_MOVES] = (int)(t / N_MOVES); }
            if (v[k].y != 0.f) { long t = e + 1; idx[t % N_MOVES] = (int)(t / N_MOVES); }
            if (v[k].z != 0.f) { long t = e + 2; idx[t % N_MOVES] = (int)(t / N_MOVES); }
            if (v[k].w != 0.f) { long t = e + 3; idx[t % N_MOVES] = (int)(t / N_MOVES); }
        }
    }
}

// ---------------------------------------------------------------------------
// Kernel 2: each block gathers ROWS=2 consecutive batch rows.
// Plain coalesced float4 loads (x stays L2-resident across replays) into smem,
// then branchless float4 streaming stores (block span is 16B-aligned).
// ---------------------------------------------------------------------------
__global__ __launch_bounds__(256)
void gather_kernel(const float* __restrict__ x,
                   const int* __restrict__ idx,
                   float* __restrict__ out) {
    __shared__ float rows[ROWS * FLAT];   // 37376 B

    const int tid = threadIdx.x;
    const size_t b0 = (size_t)blockIdx.x * ROWS;

    // Contiguous fill: 2336 float4s (~9.1 per thread).
    const float4* xr = (const float4*)(x + b0 * FLAT);
    float4* rs = (float4*)rows;
    #pragma unroll
    for (int i = tid; i < PAIR4; i += 256) {
        rs[i] = xr[i];
    }
    __syncthreads();

    // 929 float4 streaming stores per block (~3.6 per thread).
    float4* ob4 = (float4*)(out + b0 * N_MOVES);
    #pragma unroll
    for (int j = tid; j < OUT4; j += 256) {
        int e0 = 4 * j;
        float v[4];
        #pragma unroll
        for (int k = 0; k < 4; k++) {
            int e = e0 + k;
            int r = (e >= N_MOVES) ? 1 : 0;      // row within the pair
            int c = e - r * N_MOVES;
            v[k] = rows[r * FLAT + __ldg(&idx[c])];
        }
        __stcs(&ob4[j], make_float4(v[0], v[1], v[2], v[3]));
    }
}

extern "C" void kernel_launch(void* const* d_in, const int* in_sizes, int n_in,
                              void* d_out, int out_size) {
    const float* x = (const float*)d_in[0];          // [4096, 73, 8, 8]
    const float* W = (const float*)d_in[1];          // [4672, 1858]
    float* out = (float*)d_out;                      // [4096, 1858]

    int* idx_ptr;
    cudaGetSymbolAddress((void**)&idx_ptr, g_idx);

    extract_idx_kernel<<<E_BLOCKS, 256>>>((const float4*)W, idx_ptr);
    gather_kernel<<<BATCH / ROWS, 256>>>(x, idx_ptr, out);
}

// round 9
// speedup vs baseline: 1.2574x; 1.2574x over previous
#include <cuda_runtime.h>
#include <cstdint>

#define N_PLANES 73
#define BOARD 8
#define FLAT (N_PLANES * BOARD * BOARD)   // 4672
#define N_MOVES 1858
#define IDX_PAD 1864                      // padded so IDX_BYTES % 16 == 0
#define IDX_BYTES (IDX_PAD * 4)           // 7456
#define BATCH 4096
#define ROWS 2                            // batch rows per gather block
#define OUT4 ((ROWS * N_MOVES) / 4)       // 929 float4 stores per block
#define PAIR_BYTES (ROWS * FLAT * 4)      // 37376

#define N4 ((FLAT * N_MOVES) / 4)         // 2,170,144 float4s in W
#define E_CHUNK 2048                      // float4s per extract block (8/thread)
#define E_BLOCKS ((N4 + E_CHUNK - 1) / E_CHUNK)   // 1060

// Scratch for extracted one-hot row indices (device mallocs banned).
// Padded + 16B-aligned so TMA bulk copy of IDX_BYTES is legal.
__device__ __align__(16) int g_idx[IDX_PAD];

// ----------------------------- PTX helpers ---------------------------------
__device__ __forceinline__ uint32_t smem_u32(const void* p) {
    uint32_t a;
    asm("{ .reg .u64 t; cvta.to.shared.u64 t, %1; cvt.u32.u64 %0, t; }"
        : "=r"(a) : "l"(p));
    return a;
}
__device__ __forceinline__ void mbar_init(uint32_t mbar, uint32_t cnt) {
    asm volatile("mbarrier.init.shared.b64 [%0], %1;" :: "r"(mbar), "r"(cnt));
}
__device__ __forceinline__ void mbar_expect_tx(uint32_t mbar, uint32_t bytes) {
    asm volatile("mbarrier.arrive.expect_tx.shared.b64 _, [%0], %1;"
                 :: "r"(mbar), "r"(bytes));
}
__device__ __forceinline__ void bulk_g2s(uint32_t dst, const void* src,
                                         uint32_t bytes, uint32_t mbar) {
    asm volatile(
        "cp.async.bulk.shared::cta.global.mbarrier::complete_tx::bytes "
        "[%0], [%1], %2, [%3];"
        :: "r"(dst), "l"(src), "r"(bytes), "r"(mbar) : "memory");
}
__device__ __forceinline__ void mbar_wait(uint32_t mbar, uint32_t parity) {
    asm volatile(
        "{\n\t"
        ".reg .pred P;\n\t"
        "WAIT_%=:\n\t"
        "mbarrier.try_wait.parity.acquire.cta.shared::cta.b64 P, [%0], %1, 0x989680;\n\t"
        "@P bra.uni DONE_%=;\n\t"
        "bra.uni WAIT_%=;\n\t"
        "DONE_%=:\n\t"
        "}"
        :: "r"(mbar), "r"(parity) : "memory");
}

// ---------------------------------------------------------------------------
// Kernel 1: recover idx[j] = r with W[r][j] == 1.0.
// Each block owns 2048 contiguous float4s; 8 back-to-back coalesced loads per
// thread (MLP=8). Plain loads -> W stays L2-resident across graph replays.
// ---------------------------------------------------------------------------
__global__ __launch_bounds__(256)
void extract_idx_kernel(const float4* __restrict__ W4,
                        int* __restrict__ idx) {
    const int base = blockIdx.x * E_CHUNK + threadIdx.x;

    float4 v[8];
    #pragma unroll
    for (int k = 0; k < 8; k++) {
        int i = base + k * 256;
        v[k] = (i < N4) ? W4[i] : make_float4(0.f, 0.f, 0.f, 0.f);
    }

    #pragma unroll
    for (int k = 0; k < 8; k++) {
        if (v[k].x != 0.f || v[k].y != 0.f || v[k].z != 0.f || v[k].w != 0.f) {
            long e = (long)(base + k * 256) * 4;
            if (v[k].x != 0.f) { long t = e;     idx[t % N_MOVES] = (int)(t / N_MOVES); }
            if (v[k].y != 0.f) { long t = e + 1; idx[t % N_MOVES] = (int)(t / N_MOVES); }
            if (v[k].z != 0.f) { long t = e + 2; idx[t % N_MOVES] = (int)(t / N_MOVES); }
            if (v[k].w != 0.f) { long t = e + 3; idx[t % N_MOVES] = (int)(t / N_MOVES); }
        }
    }
}

// ---------------------------------------------------------------------------
// Kernel 2: each block gathers ROWS=2 consecutive batch rows.
// TMA bulk copies stage the row pair AND the idx table into smem — the SM
// issues ~2 instructions for 44.8 KB of loads instead of ~4700 LDG/STS.
// Store phase: branchless float4 streaming stores, all operands from smem.
// ---------------------------------------------------------------------------
__global__ __launch_bounds__(256)
void gather_kernel(const float* __restrict__ x,
                   float* __restrict__ out) {
    __shared__ __align__(16) float rows[ROWS * FLAT];   // 37376 B
    __shared__ __align__(16) int   sidx[IDX_PAD];       // 7456 B
    __shared__ __align__(8)  unsigned long long mbar;

    const int tid = threadIdx.x;
    const size_t b0 = (size_t)blockIdx.x * ROWS;
    const uint32_t mb = smem_u32(&mbar);

    if (tid == 0) mbar_init(mb, 1);
    __syncthreads();

    if (tid == 0) {
        mbar_expect_tx(mb, PAIR_BYTES + IDX_BYTES);
        bulk_g2s(smem_u32(rows), x + b0 * FLAT, PAIR_BYTES, mb);
        bulk_g2s(smem_u32(sidx), g_idx, IDX_BYTES, mb);
    }
    mbar_wait(mb, 0);

    // 929 float4 streaming stores per block (~3.6 per thread); block's out
    // span is 16B-aligned (2*1858*4 = 14864 ≡ 0 mod 16).
    float4* ob4 = (float4*)(out + b0 * N_MOVES);
    #pragma unroll
    for (int j = tid; j < OUT4; j += 256) {
        int e0 = 4 * j;
        float v[4];
        #pragma unroll
        for (int k = 0; k < 4; k++) {
            int e = e0 + k;
            int r = (e >= N_MOVES) ? 1 : 0;      // row within the pair
            int c = e - r * N_MOVES;
            v[k] = rows[r * FLAT + sidx[c]];
        }
        __stcs(&ob4[j], make_float4(v[0], v[1], v[2], v[3]));
    }
}

extern "C" void kernel_launch(void* const* d_in, const int* in_sizes, int n_in,
                              void* d_out, int out_size) {
    const float* x = (const float*)d_in[0];          // [4096, 73, 8, 8]
    const float* W = (const float*)d_in[1];          // [4672, 1858]
    float* out = (float*)d_out;                      // [4096, 1858]

    int* idx_ptr;
    cudaGetSymbolAddress((void**)&idx_ptr, g_idx);

    extract_idx_kernel<<<E_BLOCKS, 256>>>((const float4*)W, idx_ptr);
    gather_kernel<<<BATCH / ROWS, 256>>>(x, out);
}

// round 11
// speedup vs baseline: 1.2854x; 1.0223x over previous
#include <cuda_runtime.h>
#include <cstdint>

#define N_PLANES 73
#define BOARD 8
#define FLAT (N_PLANES * BOARD * BOARD)   // 4672
#define N_MOVES 1858
#define IDX_PAD 1872                      // u16 count, 3744 B (16B multiple)
#define IDX_BYTES (IDX_PAD * 2)           // 3744
#define BATCH 4096
#define ROWS 2                            // batch rows per gather block
#define OUT4 ((ROWS * N_MOVES) / 4)       // 929 float4 stores per block
#define PAIR_BYTES (ROWS * FLAT * 4)      // 37376

#define W_BYTES ((long)FLAT * N_MOVES * 4)        // 34,722,304
#define CHUNK_BYTES 32768                          // W chunk per extract block
#define CHUNK_F4 (CHUNK_BYTES / 16)                // 2048
#define E_BLOCKS ((int)((W_BYTES + CHUNK_BYTES - 1) / CHUNK_BYTES))  // 1060

// Scratch (device mallocs banned): one-hot row index per move, as u16.
__device__ __align__(16) unsigned short g_idx16[IDX_PAD];

// ----------------------------- PTX helpers ---------------------------------
__device__ __forceinline__ uint32_t smem_u32(const void* p) {
    uint32_t a;
    asm("{ .reg .u64 t; cvta.to.shared.u64 t, %1; cvt.u32.u64 %0, t; }"
        : "=r"(a) : "l"(p));
    return a;
}
__device__ __forceinline__ void mbar_init(uint32_t mbar, uint32_t cnt) {
    asm volatile("mbarrier.init.shared.b64 [%0], %1;" :: "r"(mbar), "r"(cnt));
}
__device__ __forceinline__ void mbar_expect_tx(uint32_t mbar, uint32_t bytes) {
    asm volatile("mbarrier.arrive.expect_tx.shared.b64 _, [%0], %1;"
                 :: "r"(mbar), "r"(bytes));
}
__device__ __forceinline__ void bulk_g2s(uint32_t dst, const void* src,
                                         uint32_t bytes, uint32_t mbar) {
    asm volatile(
        "cp.async.bulk.shared::cta.global.mbarrier::complete_tx::bytes "
        "[%0], [%1], %2, [%3];"
        :: "r"(dst), "l"(src), "r"(bytes), "r"(mbar) : "memory");
}
__device__ __forceinline__ void mbar_wait(uint32_t mbar, uint32_t parity) {
    asm volatile(
        "{\n\t"
        ".reg .pred P;\n\t"
        "WAIT_%=:\n\t"
        "mbarrier.try_wait.parity.acquire.cta.shared::cta.b64 P, [%0], %1, 0x989680;\n\t"
        "@P bra.uni DONE_%=;\n\t"
        "bra.uni WAIT_%=;\n\t"
        "DONE_%=:\n\t"
        "}"
        :: "r"(mbar), "r"(parity) : "memory");
}

// ---------------------------------------------------------------------------
// Kernel 1: recover idx16[j] = r with W[r][j] == 1.0.
// Each block TMA-copies a 32KB chunk of W into smem (2 SM-side instructions
// for 32KB, bypassing the L1tex LDG wavefront queue), then scans it with
// conflict-free float4 LDS. Only the ~1858 nonzero hits pay the div/mod.
// ---------------------------------------------------------------------------
__global__ __launch_bounds__(256)
void extract_idx_kernel(const char* __restrict__ W,
                        unsigned short* __restrict__ idx16) {
    __shared__ __align__(16) float4 buf[CHUNK_F4];   // 32768 B
    __shared__ __align__(8)  unsigned long long mbar;

    const int tid = threadIdx.x;
    const long off = (long)blockIdx.x * CHUNK_BYTES;
    const uint32_t bytes =
        (uint32_t)((W_BYTES - off < CHUNK_BYTES) ? (W_BYTES - off) : CHUNK_BYTES);
    const uint32_t mb = smem_u32(&mbar);

    if (tid == 0) mbar_init(mb, 1);
    __syncthreads();
    if (tid == 0) {
        mbar_expect_tx(mb, bytes);
        bulk_g2s(smem_u32(buf), W + off, bytes, mb);
    }
    mbar_wait(mb, 0);

    const int nf4 = bytes / 16;
    const int ebase = (int)(off / 4);                // element offset of chunk
    #pragma unroll
    for (int i = tid; i < CHUNK_F4; i += 256) {
        if (i >= nf4) break;
        float4 v = buf[i];
        if (v.x != 0.f || v.y != 0.f || v.z != 0.f || v.w != 0.f) {
            int e = ebase + 4 * i;
            if (v.x != 0.f) { int t = e;     idx16[t % N_MOVES] = (unsigned short)(t / N_MOVES); }
            if (v.y != 0.f) { int t = e + 1; idx16[t % N_MOVES] = (unsigned short)(t / N_MOVES); }
            if (v.z != 0.f) { int t = e + 2; idx16[t % N_MOVES] = (unsigned short)(t / N_MOVES); }
            if (v.w != 0.f) { int t = e + 3; idx16[t % N_MOVES] = (unsigned short)(t / N_MOVES); }
        }
    }
}

// ---------------------------------------------------------------------------
// Kernel 2: each block gathers ROWS=2 consecutive batch rows.
// TMA bulk copies stage the row pair AND the u16 idx table into smem; store
// phase is branchless float4 streaming stores, all operands from smem.
// ---------------------------------------------------------------------------
__global__ __launch_bounds__(256)
void gather_kernel(const float* __restrict__ x,
                   float* __restrict__ out) {
    __shared__ __align__(16) float rows[ROWS * FLAT];        // 37376 B
    __shared__ __align__(16) unsigned short sidx[IDX_PAD];   // 3744 B
    __shared__ __align__(8)  unsigned long long mbar;

    const int tid = threadIdx.x;
    const size_t b0 = (size_t)blockIdx.x * ROWS;
    const uint32_t mb = smem_u32(&mbar);

    if (tid == 0) mbar_init(mb, 1);
    __syncthreads();
    if (tid == 0) {
        mbar_expect_tx(mb, PAIR_BYTES + IDX_BYTES);
        bulk_g2s(smem_u32(rows), x + b0 * FLAT, PAIR_BYTES, mb);
        bulk_g2s(smem_u32(sidx), g_idx16, IDX_BYTES, mb);
    }
    mbar_wait(mb, 0);

    // 929 float4 streaming stores per block (~3.6 per thread); block's out
    // span is 16B-aligned (2*1858*4 = 14864 ≡ 0 mod 16).
    float4* ob4 = (float4*)(out + b0 * N_MOVES);
    #pragma unroll
    for (int j = tid; j < OUT4; j += 256) {
        int e0 = 4 * j;
        float v[4];
        #pragma unroll
        for (int k = 0; k < 4; k++) {
            int e = e0 + k;
            int r = (e >= N_MOVES) ? 1 : 0;      // row within the pair
            int c = e - r * N_MOVES;
            v[k] = rows[r * FLAT + sidx[c]];
        }
        __stcs(&ob4[j], make_float4(v[0], v[1], v[2], v[3]));
    }
}

extern "C" void kernel_launch(void* const* d_in, const int* in_sizes, int n_in,
                              void* d_out, int out_size) {
    const float* x = (const float*)d_in[0];          // [4096, 73, 8, 8]
    const float* W = (const float*)d_in[1];          // [4672, 1858]
    float* out = (float*)d_out;                      // [4096, 1858]

    unsigned short* idx_ptr;
    cudaGetSymbolAddress((void**)&idx_ptr, g_idx16);

    extract_idx_kernel<<<E_BLOCKS, 256>>>((const char*)W, idx_ptr);
    gather_kernel<<<BATCH / ROWS, 256>>>(x, out);
}

// round 12
// speedup vs baseline: 1.6355x; 1.2723x over previous
#include <cuda_runtime.h>
#include <cstdint>

#define N_PLANES 73
#define BOARD 8
#define FLAT (N_PLANES * BOARD * BOARD)   // 4672
#define N_MOVES 1858
#define IDX_PAD 1872                      // u16 count, 3744 B (16B multiple)
#define IDX_BYTES (IDX_PAD * 2)           // 3744
#define BATCH 4096
#define ROWS 2                            // batch rows per gather block
#define OUT4 ((ROWS * N_MOVES) / 4)       // 929 float4 stores per block
#define PAIR_BYTES (ROWS * FLAT * 4)      // 37376

#define W_BYTES ((long)FLAT * N_MOVES * 4)        // 34,722,304
#define CHUNK_BYTES 32768                          // W chunk per extract block
#define CHUNK_F4 (CHUNK_BYTES / 16)                // 2048
#define E_BLOCKS ((int)((W_BYTES + CHUNK_BYTES - 1) / CHUNK_BYTES))  // 1060

// Scratch (device mallocs banned): one-hot row index per move, as u16.
__device__ __align__(16) unsigned short g_idx16[IDX_PAD];

// ----------------------------- PTX helpers ---------------------------------
__device__ __forceinline__ uint32_t smem_u32(const void* p) {
    uint32_t a;
    asm("{ .reg .u64 t; cvta.to.shared.u64 t, %1; cvt.u32.u64 %0, t; }"
        : "=r"(a) : "l"(p));
    return a;
}
__device__ __forceinline__ void mbar_init(uint32_t mbar, uint32_t cnt) {
    asm volatile("mbarrier.init.shared.b64 [%0], %1;" :: "r"(mbar), "r"(cnt));
}
__device__ __forceinline__ void mbar_expect_tx(uint32_t mbar, uint32_t bytes) {
    asm volatile("mbarrier.arrive.expect_tx.shared.b64 _, [%0], %1;"
                 :: "r"(mbar), "r"(bytes));
}
// evict_last: keep src cached in L2 across graph replays (for W)
__device__ __forceinline__ void bulk_g2s_keep(uint32_t dst, const void* src,
                                              uint32_t bytes, uint32_t mbar) {
    uint64_t pol;
    asm volatile("createpolicy.fractional.L2::evict_last.b64 %0, 1.0;" : "=l"(pol));
    asm volatile(
        "cp.async.bulk.shared::cta.global.mbarrier::complete_tx::bytes.L2::cache_hint "
        "[%0], [%1], %2, [%3], %4;"
        :: "r"(dst), "l"(src), "r"(bytes), "r"(mbar), "l"(pol) : "memory");
}
// evict_first: streaming src, don't pollute L2 (for x)
__device__ __forceinline__ void bulk_g2s_stream(uint32_t dst, const void* src,
                                                uint32_t bytes, uint32_t mbar) {
    uint64_t pol;
    asm volatile("createpolicy.fractional.L2::evict_first.b64 %0, 1.0;" : "=l"(pol));
    asm volatile(
        "cp.async.bulk.shared::cta.global.mbarrier::complete_tx::bytes.L2::cache_hint "
        "[%0], [%1], %2, [%3], %4;"
        :: "r"(dst), "l"(src), "r"(bytes), "r"(mbar), "l"(pol) : "memory");
}
__device__ __forceinline__ void bulk_g2s(uint32_t dst, const void* src,
                                         uint32_t bytes, uint32_t mbar) {
    asm volatile(
        "cp.async.bulk.shared::cta.global.mbarrier::complete_tx::bytes "
        "[%0], [%1], %2, [%3];"
        :: "r"(dst), "l"(src), "r"(bytes), "r"(mbar) : "memory");
}
__device__ __forceinline__ void mbar_wait(uint32_t mbar, uint32_t parity) {
    asm volatile(
        "{\n\t"
        ".reg .pred P;\n\t"
        "WAIT_%=:\n\t"
        "mbarrier.try_wait.parity.acquire.cta.shared::cta.b64 P, [%0], %1, 0x989680;\n\t"
        "@P bra.uni DONE_%=;\n\t"
        "bra.uni WAIT_%=;\n\t"
        "DONE_%=:\n\t"
        "}"
        :: "r"(mbar), "r"(parity) : "memory");
}

// ---------------------------------------------------------------------------
// Kernel 1: recover idx16[j] = r with W[r][j] == 1.0.
// TMA-copies 32KB W chunks into smem with L2::evict_last so W (34.7 MB) stays
// L2-resident across graph replays; steady-state replays serve it from L2.
// ---------------------------------------------------------------------------
__global__ __launch_bounds__(256)
void extract_idx_kernel(const char* __restrict__ W,
                        unsigned short* __restrict__ idx16) {
    __shared__ __align__(16) float4 buf[CHUNK_F4];   // 32768 B
    __shared__ __align__(8)  unsigned long long mbar;

    const int tid = threadIdx.x;
    const long off = (long)blockIdx.x * CHUNK_BYTES;
    const uint32_t bytes =
        (uint32_t)((W_BYTES - off < CHUNK_BYTES) ? (W_BYTES - off) : CHUNK_BYTES);
    const uint32_t mb = smem_u32(&mbar);

    if (tid == 0) mbar_init(mb, 1);
    __syncthreads();
    if (tid == 0) {
        mbar_expect_tx(mb, bytes);
        bulk_g2s_keep(smem_u32(buf), W + off, bytes, mb);
    }
    mbar_wait(mb, 0);

    const int nf4 = bytes / 16;
    const int ebase = (int)(off / 4);                // element offset of chunk
    #pragma unroll
    for (int i = tid; i < CHUNK_F4; i += 256) {
        if (i >= nf4) break;
        float4 v = buf[i];
        if (v.x != 0.f || v.y != 0.f || v.z != 0.f || v.w != 0.f) {
            int e = ebase + 4 * i;
            if (v.x != 0.f) { int t = e;     idx16[t % N_MOVES] = (unsigned short)(t / N_MOVES); }
            if (v.y != 0.f) { int t = e + 1; idx16[t % N_MOVES] = (unsigned short)(t / N_MOVES); }
            if (v.z != 0.f) { int t = e + 2; idx16[t % N_MOVES] = (unsigned short)(t / N_MOVES); }
            if (v.w != 0.f) { int t = e + 3; idx16[t % N_MOVES] = (unsigned short)(t / N_MOVES); }
        }
    }
}

// ---------------------------------------------------------------------------
// Kernel 2: each block gathers ROWS=2 consecutive batch rows.
// x staged via TMA with L2::evict_first (pure stream, protects W's residency);
// idx table TMA'd with default policy (tiny, hot). Store phase: branchless
// float4 streaming stores, all operands from smem.
// ---------------------------------------------------------------------------
__global__ __launch_bounds__(256)
void gather_kernel(const float* __restrict__ x,
                   float* __restrict__ out) {
    __shared__ __align__(16) float rows[ROWS * FLAT];        // 37376 B
    __shared__ __align__(16) unsigned short sidx[IDX_PAD];   // 3744 B
    __shared__ __align__(8)  unsigned long long mbar;

    const int tid = threadIdx.x;
    const size_t b0 = (size_t)blockIdx.x * ROWS;
    const uint32_t mb = smem_u32(&mbar);

    if (tid == 0) mbar_init(mb, 1);
    __syncthreads();
    if (tid == 0) {
        mbar_expect_tx(mb, PAIR_BYTES + IDX_BYTES);
        bulk_g2s_stream(smem_u32(rows), x + b0 * FLAT, PAIR_BYTES, mb);
        bulk_g2s(smem_u32(sidx), g_idx16, IDX_BYTES, mb);
    }
    mbar_wait(mb, 0);

    // 929 float4 streaming stores per block (~3.6 per thread); block's out
    // span is 16B-aligned (2*1858*4 = 14864 ≡ 0 mod 16).
    float4* ob4 = (float4*)(out + b0 * N_MOVES);
    #pragma unroll
    for (int j = tid; j < OUT4; j += 256) {
        int e0 = 4 * j;
        float v[4];
        #pragma unroll
        for (int k = 0; k < 4; k++) {
            int e = e0 + k;
            int r = (e >= N_MOVES) ? 1 : 0;      // row within the pair
            int c = e - r * N_MOVES;
            v[k] = rows[r * FLAT + sidx[c]];
        }
        __stcs(&ob4[j], make_float4(v[0], v[1], v[2], v[3]));
    }
}

extern "C" void kernel_launch(void* const* d_in, const int* in_sizes, int n_in,
                              void* d_out, int out_size) {
    const float* x = (const float*)d_in[0];          // [4096, 73, 8, 8]
    const float* W = (const float*)d_in[1];          // [4672, 1858]
    float* out = (float*)d_out;                      // [4096, 1858]

    unsigned short* idx_ptr;
    cudaGetSymbolAddress((void**)&idx_ptr, g_idx16);

    extract_idx_kernel<<<E_BLOCKS, 256>>>((const char*)W, idx_ptr);
    gather_kernel<<<BATCH / ROWS, 256>>>(x, out);
}